// round 1
// baseline (speedup 1.0000x reference)
#include <cuda_runtime.h>

#define T_TOKENS 8192
#define D_DIM 1024
#define E_EXP 8
#define O_DIM 1024

// routing scratch (no allocations allowed -> __device__ globals)
__device__ int   g_cnt[E_EXP];
__device__ int   g_tok[E_EXP * T_TOKENS];
__device__ float g_wt [E_EXP * T_TOKENS];

__global__ void zero_cnt_kernel() {
    if (threadIdx.x < E_EXP) g_cnt[threadIdx.x] = 0;
}

// One block per token: gate logits (8 warps x warp-dot), top-2 + softmax,
// bucket-append to per-expert lists, and out[t,:] = w0*be[e0,:] + w1*be[e1,:]
__global__ void gate_kernel(const float* __restrict__ x,
                            const float* __restrict__ Wg,
                            const float* __restrict__ be,
                            float* __restrict__ out) {
    int t = blockIdx.x;
    __shared__ float xs[D_DIM];
    __shared__ float logits[E_EXP];
    __shared__ int   se[2];
    __shared__ float sw[2];

    const float* xr = x + (size_t)t * D_DIM;
    for (int i = threadIdx.x; i < D_DIM; i += blockDim.x) xs[i] = xr[i];
    __syncthreads();

    int warp = threadIdx.x >> 5, lane = threadIdx.x & 31;
    if (warp < E_EXP) {
        const float* wr = Wg + warp * D_DIM;
        float s = 0.f;
        for (int i = lane; i < D_DIM; i += 32) s += xs[i] * wr[i];
        #pragma unroll
        for (int o = 16; o > 0; o >>= 1) s += __shfl_xor_sync(0xffffffffu, s, o);
        if (lane == 0) logits[warp] = s;
    }
    __syncthreads();

    if (threadIdx.x == 0) {
        // top-2, ties -> lowest index (matches jax.lax.top_k)
        int i0 = 0; float v0 = logits[0];
        #pragma unroll
        for (int e = 1; e < E_EXP; e++)
            if (logits[e] > v0) { v0 = logits[e]; i0 = e; }
        int i1 = -1; float v1 = -3.4e38f;
        #pragma unroll
        for (int e = 0; e < E_EXP; e++) {
            if (e == i0) continue;
            if (logits[e] > v1) { v1 = logits[e]; i1 = e; }
        }
        float ex = __expf(v1 - v0);           // v1 <= v0, stable
        float inv = 1.f / (1.f + ex);
        float w0 = inv, w1 = ex * inv;

        int p0 = atomicAdd(&g_cnt[i0], 1);
        g_tok[i0 * T_TOKENS + p0] = t; g_wt[i0 * T_TOKENS + p0] = w0;
        int p1 = atomicAdd(&g_cnt[i1], 1);
        g_tok[i1 * T_TOKENS + p1] = t; g_wt[i1 * T_TOKENS + p1] = w1;

        se[0] = i0; se[1] = i1; sw[0] = w0; sw[1] = w1;
    }
    __syncthreads();

    int e0 = se[0], e1 = se[1];
    float w0 = sw[0], w1 = sw[1];
    float* orow = out + (size_t)t * O_DIM;
    const float* b0 = be + e0 * O_DIM;
    const float* b1 = be + e1 * O_DIM;
    for (int o = threadIdx.x; o < O_DIM; o += blockDim.x)
        orow[o] = w0 * b0[o] + w1 * b1[o];
}

// Gathered per-expert NT GEMM: C[tok_tile 128 x out_tile 128] = Xg * We[e]^T
// fp32 SIMT, BK=8, 8x8 micro-tile per thread, weighted atomicAdd scatter.
#define BM 128
#define BN 128
#define BK 8
#define SW (BK + 2)   // smem row pad: 2-way max bank conflict on b-frag loads

__global__ __launch_bounds__(256, 2)
void expert_gemm_kernel(const float* __restrict__ x,
                        const float* __restrict__ We,
                        float* __restrict__ out) {
    int e   = blockIdx.z;
    int cnt = g_cnt[e];
    int row0 = blockIdx.y * BM;
    if (row0 >= cnt) return;
    int o0 = blockIdx.x * BN;

    __shared__ float As[BM][SW];
    __shared__ float Bs[BN][SW];
    __shared__ int   stok[BM];
    __shared__ float swt[BM];

    int tid = threadIdx.x;
    for (int i = tid; i < BM; i += 256) {
        int r = row0 + i;
        if (r < cnt) { stok[i] = g_tok[e * T_TOKENS + r]; swt[i] = g_wt[e * T_TOKENS + r]; }
        else         { stok[i] = -1;                      swt[i] = 0.f; }
    }
    __syncthreads();

    int tx = tid & 15, ty = tid >> 4;     // 16x16 thread grid
    float acc[8][8];
    #pragma unroll
    for (int i = 0; i < 8; i++)
        #pragma unroll
        for (int j = 0; j < 8; j++) acc[i][j] = 0.f;

    int lrow = tid >> 1;                  // 0..127
    int lcol = (tid & 1) * 4;             // 0 or 4
    const float* Wbase = We + ((size_t)e << 20) + (size_t)(o0 + lrow) * D_DIM + lcol;
    int atok = stok[lrow];
    const float* Abase = (atok >= 0) ? (x + (size_t)atok * D_DIM + lcol) : nullptr;

    for (int kk = 0; kk < D_DIM; kk += BK) {
        float4 av = make_float4(0.f, 0.f, 0.f, 0.f);
        if (Abase) av = *(const float4*)(Abase + kk);
        float4 bv = *(const float4*)(Wbase + kk);
        As[lrow][lcol + 0] = av.x; As[lrow][lcol + 1] = av.y;
        As[lrow][lcol + 2] = av.z; As[lrow][lcol + 3] = av.w;
        Bs[lrow][lcol + 0] = bv.x; Bs[lrow][lcol + 1] = bv.y;
        Bs[lrow][lcol + 2] = bv.z; Bs[lrow][lcol + 3] = bv.w;
        __syncthreads();

        #pragma unroll
        for (int k = 0; k < BK; k++) {
            float a[8], b[8];
            #pragma unroll
            for (int i = 0; i < 8; i++) a[i] = As[8 * ty + i][k];
            #pragma unroll
            for (int j = 0; j < 8; j++) b[j] = Bs[8 * tx + j][k];
            #pragma unroll
            for (int i = 0; i < 8; i++)
                #pragma unroll
                for (int j = 0; j < 8; j++)
                    acc[i][j] += a[i] * b[j];
        }
        __syncthreads();
    }

    #pragma unroll
    for (int i = 0; i < 8; i++) {
        int r = 8 * ty + i;
        int tok = stok[r];
        if (tok < 0) continue;
        float w = swt[r];
        float* orow = out + (size_t)tok * O_DIM + o0 + 8 * tx;
        #pragma unroll
        for (int j = 0; j < 8; j++)
            atomicAdd(&orow[j], w * acc[i][j]);
    }
}

extern "C" void kernel_launch(void* const* d_in, const int* in_sizes, int n_in,
                              void* d_out, int out_size) {
    const float* x  = (const float*)d_in[0];   // [4,2048,1024]
    const float* Wg = (const float*)d_in[1];   // [8,1024]
    const float* We = (const float*)d_in[2];   // [8,1024,1024]
    const float* be = (const float*)d_in[3];   // [8,1024]
    float* out = (float*)d_out;                // [4,2048,1024]

    zero_cnt_kernel<<<1, 32>>>();
    gate_kernel<<<T_TOKENS, 256>>>(x, Wg, be, out);
    dim3 grid(O_DIM / BN, (T_TOKENS + BM - 1) / BM, E_EXP);
    expert_gemm_kernel<<<grid, 256>>>(x, We, out);
}

// round 4
// speedup vs baseline: 9.3940x; 9.3940x over previous
#include <cuda_runtime.h>
#include <cuda_fp16.h>
#include <cstdint>

#define T_TOKENS 8192
#define D_DIM    1024
#define E_EXP    8
#define O_DIM    1024
#define ROWS_MAX (2 * T_TOKENS + E_EXP * 128)   // 17408 (128-padded segments)

// ---------------- device scratch (no allocations allowed) ----------------
__device__ int   g_cnt[E_EXP];
__device__ int   g_off[E_EXP + 1];
__device__ int   g_exp [2 * T_TOKENS];
__device__ int   g_rank[2 * T_TOKENS];
__device__ float g_w   [2 * T_TOKENS];
__device__ __half g_xg[(size_t)ROWS_MAX * D_DIM];
__device__ __half g_we[(size_t)E_EXP * O_DIM * D_DIM];
__device__ float  g_ys[(size_t)ROWS_MAX * O_DIM];

// ---------------- helpers ----------------
__device__ __forceinline__ uint32_t smem_u32(const void* p) {
    return (uint32_t)__cvta_generic_to_shared(p);
}
__device__ __forceinline__ void cp16(uint32_t s, const void* g) {
    asm volatile("cp.async.cg.shared.global [%0], [%1], 16;" :: "r"(s), "l"(g) : "memory");
}
__device__ __forceinline__ void cp_commit() {
    asm volatile("cp.async.commit_group;" ::: "memory");
}
__device__ __forceinline__ void cp_wait1() {
    asm volatile("cp.async.wait_group 1;" ::: "memory");
}
__device__ __forceinline__ void cp_wait0() {
    asm volatile("cp.async.wait_group 0;" ::: "memory");
}

// ---------------- phase kernels ----------------
__global__ void zero_cnt_kernel() {
    if (threadIdx.x < E_EXP) g_cnt[threadIdx.x] = 0;
}

// We fp32 -> fp16. 8 floats / thread.
__global__ void convert_we_kernel(const float* __restrict__ We) {
    size_t i = ((size_t)blockIdx.x * blockDim.x + threadIdx.x) * 8;
    float4 a = *(const float4*)(We + i);
    float4 b = *(const float4*)(We + i + 4);
    __half h[8];
    h[0] = __float2half_rn(a.x); h[1] = __float2half_rn(a.y);
    h[2] = __float2half_rn(a.z); h[3] = __float2half_rn(a.w);
    h[4] = __float2half_rn(b.x); h[5] = __float2half_rn(b.y);
    h[6] = __float2half_rn(b.z); h[7] = __float2half_rn(b.w);
    *(uint4*)(g_we + i) = *(const uint4*)h;
}

// One block per token: 8 warp-dot gate logits, top-2 (ties -> lowest index),
// softmax over the 2, record (expert, rank, weight) per choice.
__global__ void gate_kernel(const float* __restrict__ x,
                            const float* __restrict__ Wg) {
    int t = blockIdx.x;
    __shared__ float xs[D_DIM];
    __shared__ float logits[E_EXP];

    const float* xr = x + (size_t)t * D_DIM;
    for (int i = threadIdx.x; i < D_DIM; i += blockDim.x) xs[i] = xr[i];
    __syncthreads();

    int warp = threadIdx.x >> 5, lane = threadIdx.x & 31;
    if (warp < E_EXP) {
        const float* wr = Wg + warp * D_DIM;
        float s = 0.f;
        for (int i = lane; i < D_DIM; i += 32) s += xs[i] * wr[i];
        #pragma unroll
        for (int o = 16; o > 0; o >>= 1) s += __shfl_xor_sync(0xffffffffu, s, o);
        if (lane == 0) logits[warp] = s;
    }
    __syncthreads();

    if (threadIdx.x == 0) {
        int i0 = 0; float v0 = logits[0];
        #pragma unroll
        for (int e = 1; e < E_EXP; e++)
            if (logits[e] > v0) { v0 = logits[e]; i0 = e; }
        int i1 = -1; float v1 = -3.4e38f;
        #pragma unroll
        for (int e = 0; e < E_EXP; e++) {
            if (e == i0) continue;
            if (logits[e] > v1) { v1 = logits[e]; i1 = e; }
        }
        float ex = __expf(v1 - v0);
        float inv = 1.f / (1.f + ex);
        float w0 = inv, w1 = ex * inv;

        int p0 = atomicAdd(&g_cnt[i0], 1);
        int p1 = atomicAdd(&g_cnt[i1], 1);
        g_exp[2 * t] = i0;     g_rank[2 * t] = p0;     g_w[2 * t] = w0;
        g_exp[2 * t + 1] = i1; g_rank[2 * t + 1] = p1; g_w[2 * t + 1] = w1;
    }
}

// 128-row padded exclusive scan of counts.
__global__ void offsets_kernel() {
    if (threadIdx.x == 0) {
        int acc = 0;
        #pragma unroll
        for (int e = 0; e < E_EXP; e++) {
            g_off[e] = acc;
            acc += (g_cnt[e] + 127) & ~127;
        }
        g_off[E_EXP] = acc;
    }
}

// Gather tokens into compact per-expert row blocks as fp16.
__global__ void pack_kernel(const float* __restrict__ x) {
    int t = blockIdx.x;
    size_t s0 = (size_t)g_off[g_exp[2 * t]]     + g_rank[2 * t];
    size_t s1 = (size_t)g_off[g_exp[2 * t + 1]] + g_rank[2 * t + 1];
    int i = threadIdx.x * 8;   // 128 threads * 8 = 1024
    const float* xr = x + (size_t)t * D_DIM + i;
    float4 a = *(const float4*)xr;
    float4 b = *(const float4*)(xr + 4);
    __half h[8];
    h[0] = __float2half_rn(a.x); h[1] = __float2half_rn(a.y);
    h[2] = __float2half_rn(a.z); h[3] = __float2half_rn(a.w);
    h[4] = __float2half_rn(b.x); h[5] = __float2half_rn(b.y);
    h[6] = __float2half_rn(b.z); h[7] = __float2half_rn(b.w);
    uint4 hv = *(const uint4*)h;
    *(uint4*)(g_xg + s0 * D_DIM + i) = hv;
    *(uint4*)(g_xg + s1 * D_DIM + i) = hv;
}

// Zero pad rows (<= 127 per expert) so GEMM tiles never see garbage.
__global__ void zero_pad_kernel() {
    int e = blockIdx.x;
    int start = g_off[e] + g_cnt[e];
    int end   = g_off[e + 1];
    int n16 = (end - start) * (D_DIM / 8);
    uint4 z = make_uint4(0, 0, 0, 0);
    for (int i = threadIdx.x; i < n16; i += blockDim.x) {
        size_t row = start + i / (D_DIM / 8);
        size_t col = (size_t)(i % (D_DIM / 8)) * 8;
        *(uint4*)(g_xg + row * D_DIM + col) = z;
    }
}

// ---------------- fp16 HMMA segmented GEMM ----------------
// Tile 128x128, BK=32, double-buffered cp.async, 8 warps (4x2), warp tile 32x64.
#define BK      32
#define RSTRIDE 40     // halves per smem row (80B): conflict-free pad
#define NCHUNK  (D_DIM / BK)   // 32

__global__ __launch_bounds__(256, 2) void expert_gemm_hmma() {
    int total = g_off[E_EXP];
    int r0 = blockIdx.y * 128;
    if (r0 >= total) return;
    int o0 = blockIdx.x * 128;
    int e = 0;
    #pragma unroll
    for (int k = 1; k < E_EXP; k++) if (r0 >= g_off[k]) e = k;

    __shared__ __half As[2][128 * RSTRIDE];
    __shared__ __half Bs[2][128 * RSTRIDE];

    int tid = threadIdx.x;
    int lane = tid & 31, warp = tid >> 5;
    int wm = warp & 3, wn = warp >> 2;      // 4x2 warp grid
    int g = lane >> 2, tig = lane & 3;

    const __half* gA = g_xg + (size_t)r0 * D_DIM;
    const __half* gB = g_we + ((size_t)e * O_DIM + o0) * D_DIM;

    uint32_t sA[2] = { smem_u32(As[0]), smem_u32(As[1]) };
    uint32_t sB[2] = { smem_u32(Bs[0]), smem_u32(Bs[1]) };

    // per-thread load slots: id = tid + 256*i -> row=id>>2 (0..127), seg=id&3
    int lrow0 = tid >> 2, lseg = tid & 3;

    auto load_chunk = [&](int c, int s) {
        #pragma unroll
        for (int i = 0; i < 2; i++) {
            int row = lrow0 + 64 * i;
            uint32_t so = (uint32_t)(row * (RSTRIDE * 2) + lseg * 16);
            const __half* ga = gA + (size_t)row * D_DIM + c * BK + lseg * 8;
            const __half* gb = gB + (size_t)row * D_DIM + c * BK + lseg * 8;
            cp16(sA[s] + so, ga);
            cp16(sB[s] + so, gb);
        }
        cp_commit();
    };

    float acc[2][8][4];
    #pragma unroll
    for (int i = 0; i < 2; i++)
        #pragma unroll
        for (int j = 0; j < 8; j++)
            #pragma unroll
            for (int q = 0; q < 4; q++) acc[i][j][q] = 0.f;

    load_chunk(0, 0);
    for (int c = 0; c < NCHUNK; c++) {
        int s = c & 1;
        if (c + 1 < NCHUNK) { load_chunk(c + 1, s ^ 1); cp_wait1(); }
        else                { cp_wait0(); }
        __syncthreads();

        #pragma unroll
        for (int kk = 0; kk < 2; kk++) {
            int kb = kk * 16 + 2 * tig;
            uint32_t a[2][4], b[8][2];
            #pragma unroll
            for (int i = 0; i < 2; i++) {
                const __half* base = &As[s][(32 * wm + 16 * i + g) * RSTRIDE + kb];
                a[i][0] = *(const uint32_t*)(base);
                a[i][1] = *(const uint32_t*)(base + 8 * RSTRIDE);
                a[i][2] = *(const uint32_t*)(base + 8);
                a[i][3] = *(const uint32_t*)(base + 8 * RSTRIDE + 8);
            }
            #pragma unroll
            for (int j = 0; j < 8; j++) {
                const __half* base = &Bs[s][(64 * wn + 8 * j + g) * RSTRIDE + kb];
                b[j][0] = *(const uint32_t*)(base);
                b[j][1] = *(const uint32_t*)(base + 8);
            }
            #pragma unroll
            for (int i = 0; i < 2; i++)
                #pragma unroll
                for (int j = 0; j < 8; j++)
                    asm volatile(
                        "mma.sync.aligned.m16n8k16.row.col.f32.f16.f16.f32 "
                        "{%0,%1,%2,%3}, {%4,%5,%6,%7}, {%8,%9}, {%0,%1,%2,%3};"
                        : "+f"(acc[i][j][0]), "+f"(acc[i][j][1]),
                          "+f"(acc[i][j][2]), "+f"(acc[i][j][3])
                        : "r"(a[i][0]), "r"(a[i][1]), "r"(a[i][2]), "r"(a[i][3]),
                          "r"(b[j][0]), "r"(b[j][1]));
        }
        __syncthreads();
    }

    // epilogue: c0,c1 -> (row g, cols 2tig,2tig+1); c2,c3 -> row g+8
    #pragma unroll
    for (int i = 0; i < 2; i++) {
        int rbase = r0 + 32 * wm + 16 * i + g;
        #pragma unroll
        for (int j = 0; j < 8; j++) {
            int col = o0 + 64 * wn + 8 * j + 2 * tig;
            float2 v0 = make_float2(acc[i][j][0], acc[i][j][1]);
            float2 v1 = make_float2(acc[i][j][2], acc[i][j][3]);
            *(float2*)(g_ys + (size_t)rbase * O_DIM + col) = v0;
            *(float2*)(g_ys + (size_t)(rbase + 8) * O_DIM + col) = v1;
        }
    }
}

// out[t,:] = w0*(ys[s0,:] + be[e0,:]) + w1*(ys[s1,:] + be[e1,:])
__global__ void combine_kernel(const float* __restrict__ be,
                               float* __restrict__ out) {
    int t = blockIdx.x;
    int e0 = g_exp[2 * t], e1 = g_exp[2 * t + 1];
    float w0 = g_w[2 * t], w1 = g_w[2 * t + 1];
    size_t s0 = (size_t)g_off[e0] + g_rank[2 * t];
    size_t s1 = (size_t)g_off[e1] + g_rank[2 * t + 1];
    int o = threadIdx.x * 4;
    float4 y0 = *(const float4*)(g_ys + s0 * O_DIM + o);
    float4 y1 = *(const float4*)(g_ys + s1 * O_DIM + o);
    float4 b0 = *(const float4*)(be + (size_t)e0 * O_DIM + o);
    float4 b1 = *(const float4*)(be + (size_t)e1 * O_DIM + o);
    float4 r;
    r.x = w0 * (y0.x + b0.x) + w1 * (y1.x + b1.x);
    r.y = w0 * (y0.y + b0.y) + w1 * (y1.y + b1.y);
    r.z = w0 * (y0.z + b0.z) + w1 * (y1.z + b1.z);
    r.w = w0 * (y0.w + b0.w) + w1 * (y1.w + b1.w);
    *(float4*)(out + (size_t)t * O_DIM + o) = r;
}

extern "C" void kernel_launch(void* const* d_in, const int* in_sizes, int n_in,
                              void* d_out, int out_size) {
    const float* x  = (const float*)d_in[0];   // [4,2048,1024]
    const float* Wg = (const float*)d_in[1];   // [8,1024]
    const float* We = (const float*)d_in[2];   // [8,1024,1024]
    const float* be = (const float*)d_in[3];   // [8,1024]
    float* out = (float*)d_out;                // [4,2048,1024]

    zero_cnt_kernel<<<1, 32>>>();
    convert_we_kernel<<<4096, 256>>>(We);
    gate_kernel<<<T_TOKENS, 256>>>(x, Wg);
    offsets_kernel<<<1, 32>>>();
    pack_kernel<<<T_TOKENS, 128>>>(x);
    zero_pad_kernel<<<E_EXP, 256>>>();
    dim3 grid(O_DIM / 128, ROWS_MAX / 128, 1);
    expert_gemm_hmma<<<grid, 256>>>();
    combine_kernel<<<T_TOKENS, 256>>>(be, out);
}

// round 5
// speedup vs baseline: 9.4582x; 1.0068x over previous
#include <cuda_runtime.h>
#include <cuda_fp16.h>
#include <cstdint>

#define T_TOKENS 8192
#define D_DIM    1024
#define E_EXP    8
#define O_DIM    1024
#define CAP      8192                      // fixed rows per expert segment
#define ROWS_CAP (E_EXP * CAP)             // 65536

// ---------------- device scratch (no allocations allowed) ----------------
__device__ int   g_cnt[E_EXP];
__device__ int   g_exp [2 * T_TOKENS];
__device__ int   g_rank[2 * T_TOKENS];
__device__ float g_w   [2 * T_TOKENS];
__device__ __half g_xg[(size_t)ROWS_CAP * D_DIM];
__device__ __half g_we[(size_t)E_EXP * O_DIM * D_DIM];
__device__ float  g_ys[(size_t)ROWS_CAP * O_DIM];

// ---------------- helpers ----------------
__device__ __forceinline__ uint32_t smem_u32(const void* p) {
    return (uint32_t)__cvta_generic_to_shared(p);
}
__device__ __forceinline__ void cp16(uint32_t s, const void* g) {
    asm volatile("cp.async.cg.shared.global [%0], [%1], 16;" :: "r"(s), "l"(g) : "memory");
}
__device__ __forceinline__ void cp_commit() {
    asm volatile("cp.async.commit_group;" ::: "memory");
}

// ---------------- phase kernels ----------------
// We fp32 -> fp16 (8 floats / thread); block 0 also zeroes the routing counters.
__global__ void convert_we_kernel(const float* __restrict__ We) {
    if (blockIdx.x == 0 && threadIdx.x < E_EXP) g_cnt[threadIdx.x] = 0;
    size_t i = ((size_t)blockIdx.x * blockDim.x + threadIdx.x) * 8;
    float4 a = *(const float4*)(We + i);
    float4 b = *(const float4*)(We + i + 4);
    __half h[8];
    h[0] = __float2half_rn(a.x); h[1] = __float2half_rn(a.y);
    h[2] = __float2half_rn(a.z); h[3] = __float2half_rn(a.w);
    h[4] = __float2half_rn(b.x); h[5] = __float2half_rn(b.y);
    h[6] = __float2half_rn(b.z); h[7] = __float2half_rn(b.w);
    *(uint4*)(g_we + i) = *(const uint4*)h;
}

// Gate: 32 tokens per block, Wg staged once in smem, one warp -> 4 tokens.
__global__ __launch_bounds__(256) void gate_kernel(const float* __restrict__ x,
                                                   const float* __restrict__ Wg) {
    __shared__ float wgs[E_EXP * D_DIM];    // 32 KB
    int tid = threadIdx.x;
    for (int i = tid; i < E_EXP * D_DIM; i += 256) wgs[i] = Wg[i];
    __syncthreads();

    int warp = tid >> 5, lane = tid & 31;
    #pragma unroll
    for (int q = 0; q < 4; q++) {
        int t = blockIdx.x * 32 + warp * 4 + q;
        const float* xr = x + (size_t)t * D_DIM;
        float acc[E_EXP];
        #pragma unroll
        for (int e = 0; e < E_EXP; e++) acc[e] = 0.f;
        for (int k = 0; k < D_DIM / 32; k++) {
            float xv = xr[k * 32 + lane];
            #pragma unroll
            for (int e = 0; e < E_EXP; e++)
                acc[e] += xv * wgs[e * D_DIM + k * 32 + lane];
        }
        #pragma unroll
        for (int e = 0; e < E_EXP; e++)
            #pragma unroll
            for (int o = 16; o > 0; o >>= 1)
                acc[e] += __shfl_xor_sync(0xffffffffu, acc[e], o);

        if (lane == 0) {
            int i0 = 0; float v0 = acc[0];
            #pragma unroll
            for (int e = 1; e < E_EXP; e++)
                if (acc[e] > v0) { v0 = acc[e]; i0 = e; }
            int i1 = -1; float v1 = -3.4e38f;
            #pragma unroll
            for (int e = 0; e < E_EXP; e++) {
                if (e == i0) continue;
                if (acc[e] > v1) { v1 = acc[e]; i1 = e; }
            }
            float ex = __expf(v1 - v0);
            float inv = 1.f / (1.f + ex);
            float w0 = inv, w1 = ex * inv;
            int p0 = atomicAdd(&g_cnt[i0], 1);
            int p1 = atomicAdd(&g_cnt[i1], 1);
            g_exp[2 * t] = i0;     g_rank[2 * t] = p0;     g_w[2 * t] = w0;
            g_exp[2 * t + 1] = i1; g_rank[2 * t + 1] = p1; g_w[2 * t + 1] = w1;
        }
    }
}

// Pack tokens into fixed-capacity per-expert segments (fp16); the last E_EXP
// blocks zero each expert's pad rows up to the next 128 multiple.
__global__ __launch_bounds__(128) void pack_kernel(const float* __restrict__ x) {
    if (blockIdx.x >= T_TOKENS) {
        int e = blockIdx.x - T_TOKENS;
        int start = g_cnt[e];
        int end   = (start + 127) & ~127;
        int n = (end - start) * (D_DIM / 8);     // uint4 count
        uint4 z = make_uint4(0, 0, 0, 0);
        for (int i = threadIdx.x; i < n; i += 128) {
            size_t row = (size_t)e * CAP + start + i / (D_DIM / 8);
            size_t col = (size_t)(i % (D_DIM / 8)) * 8;
            *(uint4*)(g_xg + row * D_DIM + col) = z;
        }
        return;
    }
    int t = blockIdx.x;
    size_t s0 = (size_t)g_exp[2 * t]     * CAP + g_rank[2 * t];
    size_t s1 = (size_t)g_exp[2 * t + 1] * CAP + g_rank[2 * t + 1];
    int i = threadIdx.x * 8;
    const float* xr = x + (size_t)t * D_DIM + i;
    float4 a = *(const float4*)xr;
    float4 b = *(const float4*)(xr + 4);
    __half h[8];
    h[0] = __float2half_rn(a.x); h[1] = __float2half_rn(a.y);
    h[2] = __float2half_rn(a.z); h[3] = __float2half_rn(a.w);
    h[4] = __float2half_rn(b.x); h[5] = __float2half_rn(b.y);
    h[6] = __float2half_rn(b.z); h[7] = __float2half_rn(b.w);
    uint4 hv = *(const uint4*)h;
    *(uint4*)(g_xg + s0 * D_DIM + i) = hv;
    *(uint4*)(g_xg + s1 * D_DIM + i) = hv;
}

// ---------------- fp16 HMMA segmented GEMM ----------------
// Tile 128x128, BK=32, 3-stage cp.async pipeline, 8 warps (4x2), warp 32x64.
#define BK       32
#define RSTRIDE  40                         // halves per smem row (80B pad)
#define NCHUNK   (D_DIM / BK)               // 32
#define TILE_H   (128 * RSTRIDE)            // 5120 halves per tile
#define STAGE_H  (2 * TILE_H)               // A then B
#define STAGE_B  (STAGE_H * 2)              // bytes
#define GEMM_SMEM (3 * STAGE_B)             // 61440

__global__ __launch_bounds__(256, 2) void expert_gemm_hmma() {
    int e   = blockIdx.y >> 6;              // 64 tiles per expert segment
    int lr0 = (blockIdx.y & 63) * 128;
    if (lr0 >= g_cnt[e]) return;
    int r0 = e * CAP + lr0;
    int o0 = blockIdx.x * 128;

    extern __shared__ __half sm[];
    uint32_t sbase = smem_u32(sm);

    int tid = threadIdx.x;
    int lane = tid & 31, warp = tid >> 5;
    int wm = warp & 3, wn = warp >> 2;
    int g = lane >> 2, tig = lane & 3;

    const __half* gA = g_xg + (size_t)r0 * D_DIM;
    const __half* gB = g_we + ((size_t)e * O_DIM + o0) * D_DIM;

    int lrow0 = tid >> 2, lseg = tid & 3;

    auto load_chunk = [&](int c, int s) {
        uint32_t sA = sbase + (uint32_t)s * STAGE_B;
        uint32_t sB = sA + TILE_H * 2;
        #pragma unroll
        for (int i = 0; i < 2; i++) {
            int row = lrow0 + 64 * i;
            uint32_t so = (uint32_t)(row * (RSTRIDE * 2) + lseg * 16);
            cp16(sA + so, gA + (size_t)row * D_DIM + c * BK + lseg * 8);
            cp16(sB + so, gB + (size_t)row * D_DIM + c * BK + lseg * 8);
        }
        cp_commit();
    };

    float acc[2][8][4];
    #pragma unroll
    for (int i = 0; i < 2; i++)
        #pragma unroll
        for (int j = 0; j < 8; j++)
            #pragma unroll
            for (int q = 0; q < 4; q++) acc[i][j][q] = 0.f;

    load_chunk(0, 0);
    load_chunk(1, 1);

    for (int c = 0; c < NCHUNK; c++) {
        int s = c % 3;
        if (c < NCHUNK - 1)
            asm volatile("cp.async.wait_group 1;" ::: "memory");
        else
            asm volatile("cp.async.wait_group 0;" ::: "memory");
        __syncthreads();
        if (c + 2 < NCHUNK) load_chunk(c + 2, (c + 2) % 3);

        const __half* Asm = sm + s * STAGE_H;
        const __half* Bsm = Asm + TILE_H;
        #pragma unroll
        for (int kk = 0; kk < 2; kk++) {
            int kb = kk * 16 + 2 * tig;
            uint32_t a[2][4], b[8][2];
            #pragma unroll
            for (int i = 0; i < 2; i++) {
                const __half* base = Asm + (32 * wm + 16 * i + g) * RSTRIDE + kb;
                a[i][0] = *(const uint32_t*)(base);
                a[i][1] = *(const uint32_t*)(base + 8 * RSTRIDE);
                a[i][2] = *(const uint32_t*)(base + 8);
                a[i][3] = *(const uint32_t*)(base + 8 * RSTRIDE + 8);
            }
            #pragma unroll
            for (int j = 0; j < 8; j++) {
                const __half* base = Bsm + (64 * wn + 8 * j + g) * RSTRIDE + kb;
                b[j][0] = *(const uint32_t*)(base);
                b[j][1] = *(const uint32_t*)(base + 8);
            }
            #pragma unroll
            for (int i = 0; i < 2; i++)
                #pragma unroll
                for (int j = 0; j < 8; j++)
                    asm volatile(
                        "mma.sync.aligned.m16n8k16.row.col.f32.f16.f16.f32 "
                        "{%0,%1,%2,%3}, {%4,%5,%6,%7}, {%8,%9}, {%0,%1,%2,%3};"
                        : "+f"(acc[i][j][0]), "+f"(acc[i][j][1]),
                          "+f"(acc[i][j][2]), "+f"(acc[i][j][3])
                        : "r"(a[i][0]), "r"(a[i][1]), "r"(a[i][2]), "r"(a[i][3]),
                          "r"(b[j][0]), "r"(b[j][1]));
        }
        __syncthreads();
    }

    #pragma unroll
    for (int i = 0; i < 2; i++) {
        int rbase = r0 + 32 * wm + 16 * i + g;
        #pragma unroll
        for (int j = 0; j < 8; j++) {
            int col = o0 + 64 * wn + 8 * j + 2 * tig;
            float2 v0 = make_float2(acc[i][j][0], acc[i][j][1]);
            float2 v1 = make_float2(acc[i][j][2], acc[i][j][3]);
            *(float2*)(g_ys + (size_t)rbase * O_DIM + col) = v0;
            *(float2*)(g_ys + (size_t)(rbase + 8) * O_DIM + col) = v1;
        }
    }
}

// out[t,:] = w0*(ys[s0,:] + be[e0,:]) + w1*(ys[s1,:] + be[e1,:])
__global__ __launch_bounds__(256) void combine_kernel(const float* __restrict__ be,
                                                      float* __restrict__ out) {
    int t = blockIdx.x;
    int e0 = g_exp[2 * t], e1 = g_exp[2 * t + 1];
    float w0 = g_w[2 * t], w1 = g_w[2 * t + 1];
    size_t s0 = (size_t)e0 * CAP + g_rank[2 * t];
    size_t s1 = (size_t)e1 * CAP + g_rank[2 * t + 1];
    int o = threadIdx.x * 4;
    float4 y0 = *(const float4*)(g_ys + s0 * O_DIM + o);
    float4 y1 = *(const float4*)(g_ys + s1 * O_DIM + o);
    float4 b0 = *(const float4*)(be + (size_t)e0 * O_DIM + o);
    float4 b1 = *(const float4*)(be + (size_t)e1 * O_DIM + o);
    float4 r;
    r.x = w0 * (y0.x + b0.x) + w1 * (y1.x + b1.x);
    r.y = w0 * (y0.y + b0.y) + w1 * (y1.y + b1.y);
    r.z = w0 * (y0.z + b0.z) + w1 * (y1.z + b1.z);
    r.w = w0 * (y0.w + b0.w) + w1 * (y1.w + b1.w);
    *(float4*)(out + (size_t)t * O_DIM + o) = r;
}

extern "C" void kernel_launch(void* const* d_in, const int* in_sizes, int n_in,
                              void* d_out, int out_size) {
    const float* x  = (const float*)d_in[0];   // [4,2048,1024]
    const float* Wg = (const float*)d_in[1];   // [8,1024]
    const float* We = (const float*)d_in[2];   // [8,1024,1024]
    const float* be = (const float*)d_in[3];   // [8,1024]
    float* out = (float*)d_out;                // [4,2048,1024]

    static int smem_set = 0;
    if (!smem_set) {
        cudaFuncSetAttribute(expert_gemm_hmma,
                             cudaFuncAttributeMaxDynamicSharedMemorySize, GEMM_SMEM);
        smem_set = 1;
    }

    convert_we_kernel<<<4096, 256>>>(We);
    gate_kernel<<<T_TOKENS / 32, 256>>>(x, Wg);
    pack_kernel<<<T_TOKENS + E_EXP, 128>>>(x);
    dim3 grid(O_DIM / 128, ROWS_CAP / 128, 1);
    expert_gemm_hmma<<<grid, 256, GEMM_SMEM>>>();
    combine_kernel<<<T_TOKENS, 256>>>(be, out);
}

// round 6
// speedup vs baseline: 11.3005x; 1.1948x over previous
#include <cuda_runtime.h>
#include <cuda_fp16.h>
#include <cstdint>

#define T_TOKENS 8192
#define D_DIM    1024
#define E_EXP    8
#define O_DIM    1024
#define CAP      8192
#define ROWS_CAP (E_EXP * CAP)

// ---------------- device scratch (no allocations allowed) ----------------
__device__ int   g_cnt[E_EXP];
__device__ int   g_exp [2 * T_TOKENS];
__device__ int   g_rank[2 * T_TOKENS];
__device__ float g_w   [2 * T_TOKENS];
__device__ int   g_rows[ROWS_CAP];                       // segment slot -> token (T_TOKENS = zero row)
__device__ __half g_xh[(size_t)(T_TOKENS + 8) * D_DIM];  // fp16 tokens + zero rows (never written)
__device__ __half g_we[(size_t)E_EXP * O_DIM * D_DIM];
__device__ float  g_ys[(size_t)ROWS_CAP * O_DIM];

// ---------------- helpers ----------------
__device__ __forceinline__ uint32_t smem_u32(const void* p) {
    return (uint32_t)__cvta_generic_to_shared(p);
}
__device__ __forceinline__ void cp16(uint32_t s, const void* g) {
    asm volatile("cp.async.cg.shared.global [%0], [%1], 16;" :: "r"(s), "l"(g) : "memory");
}
__device__ __forceinline__ void cp_commit() {
    asm volatile("cp.async.commit_group;" ::: "memory");
}
#define LDSM4(r0, r1, r2, r3, addr) \
    asm volatile("ldmatrix.sync.aligned.m8n8.x4.shared.b16 {%0,%1,%2,%3}, [%4];" \
                 : "=r"(r0), "=r"(r1), "=r"(r2), "=r"(r3) : "r"(addr))

// ---------------- phase kernels ----------------
// We fp32 -> fp16 (8 floats / thread); block 0 also zeroes routing counters.
__global__ void convert_we_kernel(const float* __restrict__ We) {
    if (blockIdx.x == 0 && threadIdx.x < E_EXP) g_cnt[threadIdx.x] = 0;
    size_t i = ((size_t)blockIdx.x * blockDim.x + threadIdx.x) * 8;
    float4 a = *(const float4*)(We + i);
    float4 b = *(const float4*)(We + i + 4);
    __half h[8];
    h[0] = __float2half_rn(a.x); h[1] = __float2half_rn(a.y);
    h[2] = __float2half_rn(a.z); h[3] = __float2half_rn(a.w);
    h[4] = __float2half_rn(b.x); h[5] = __float2half_rn(b.y);
    h[6] = __float2half_rn(b.z); h[7] = __float2half_rn(b.w);
    *(uint4*)(g_we + i) = *(const uint4*)h;
}

// x fp32 -> fp16 in token order (routing-independent, no duplication).
__global__ void convert_x_kernel(const float* __restrict__ x) {
    size_t i = ((size_t)blockIdx.x * blockDim.x + threadIdx.x) * 8;
    float4 a = *(const float4*)(x + i);
    float4 b = *(const float4*)(x + i + 4);
    __half h[8];
    h[0] = __float2half_rn(a.x); h[1] = __float2half_rn(a.y);
    h[2] = __float2half_rn(a.z); h[3] = __float2half_rn(a.w);
    h[4] = __float2half_rn(b.x); h[5] = __float2half_rn(b.y);
    h[6] = __float2half_rn(b.z); h[7] = __float2half_rn(b.w);
    *(uint4*)(g_xh + i) = *(const uint4*)h;
}

// Gate: 32 tokens/block, Wg staged in smem, one warp -> 4 tokens.
// Records per-choice (expert, rank, weight) and segment-slot -> token index.
__global__ __launch_bounds__(256) void gate_kernel(const float* __restrict__ x,
                                                   const float* __restrict__ Wg) {
    __shared__ float wgs[E_EXP * D_DIM];
    int tid = threadIdx.x;
    for (int i = tid; i < E_EXP * D_DIM; i += 256) wgs[i] = Wg[i];
    __syncthreads();

    int warp = tid >> 5, lane = tid & 31;
    #pragma unroll
    for (int q = 0; q < 4; q++) {
        int t = blockIdx.x * 32 + warp * 4 + q;
        const float* xr = x + (size_t)t * D_DIM;
        float acc[E_EXP];
        #pragma unroll
        for (int e = 0; e < E_EXP; e++) acc[e] = 0.f;
        for (int k = 0; k < D_DIM / 32; k++) {
            float xv = xr[k * 32 + lane];
            #pragma unroll
            for (int e = 0; e < E_EXP; e++)
                acc[e] += xv * wgs[e * D_DIM + k * 32 + lane];
        }
        #pragma unroll
        for (int e = 0; e < E_EXP; e++)
            #pragma unroll
            for (int o = 16; o > 0; o >>= 1)
                acc[e] += __shfl_xor_sync(0xffffffffu, acc[e], o);

        if (lane == 0) {
            int i0 = 0; float v0 = acc[0];
            #pragma unroll
            for (int e = 1; e < E_EXP; e++)
                if (acc[e] > v0) { v0 = acc[e]; i0 = e; }
            int i1 = -1; float v1 = -3.4e38f;
            #pragma unroll
            for (int e = 0; e < E_EXP; e++) {
                if (e == i0) continue;
                if (acc[e] > v1) { v1 = acc[e]; i1 = e; }
            }
            float ex = __expf(v1 - v0);
            float inv = 1.f / (1.f + ex);
            int p0 = atomicAdd(&g_cnt[i0], 1);
            int p1 = atomicAdd(&g_cnt[i1], 1);
            g_exp[2 * t] = i0;     g_rank[2 * t] = p0;     g_w[2 * t] = inv;
            g_exp[2 * t + 1] = i1; g_rank[2 * t + 1] = p1; g_w[2 * t + 1] = ex * inv;
            g_rows[i0 * CAP + p0] = t;
            g_rows[i1 * CAP + p1] = t;
        }
    }
}

// Fill pad slots (count -> next 128 multiple) with the zero-row index.
__global__ void pad_idx_kernel() {
    int e = blockIdx.x;
    int start = g_cnt[e];
    int end   = (start + 127) & ~127;
    for (int i = threadIdx.x; i < end - start; i += blockDim.x)
        g_rows[e * CAP + start + i] = T_TOKENS;
}

// ---------------- fp16 HMMA segmented GEMM (gathered A, ldmatrix frags) ----
#define BK       32
#define RSTRIDE  40                         // halves per smem row (80B pad)
#define NCHUNK   (D_DIM / BK)               // 32
#define TILE_H   (128 * RSTRIDE)
#define STAGE_B  (2 * TILE_H * 2)           // A tile + B tile, bytes
#define GEMM_SMEM (3 * STAGE_B)             // 61440

__global__ __launch_bounds__(256, 2) void expert_gemm_hmma() {
    int e   = blockIdx.y >> 6;
    int lr0 = (blockIdx.y & 63) * 128;
    if (lr0 >= g_cnt[e]) return;
    int r0 = e * CAP + lr0;
    int o0 = blockIdx.x * 128;

    __shared__ int stok[128];
    extern __shared__ __half sm[];
    uint32_t sbase = smem_u32(sm);

    int tid = threadIdx.x;
    int lane = tid & 31, warp = tid >> 5;
    int wm = warp & 3, wn = warp >> 2;

    if (tid < 128) stok[tid] = g_rows[r0 + tid];
    __syncthreads();

    // loader assignment: row = tid>>2 (+64), 16B seg = tid&3
    int lrow0 = tid >> 2, lseg = tid & 3;
    const __half* pA[2];
    const __half* pB[2];
    #pragma unroll
    for (int i = 0; i < 2; i++) {
        int row = lrow0 + 64 * i;
        pA[i] = g_xh + (size_t)stok[row] * D_DIM + lseg * 8;
        pB[i] = g_we + ((size_t)e * O_DIM + o0 + row) * D_DIM + lseg * 8;
    }
    uint32_t so[2];
    #pragma unroll
    for (int i = 0; i < 2; i++)
        so[i] = (uint32_t)((lrow0 + 64 * i) * (RSTRIDE * 2) + lseg * 16);

    auto load_chunk = [&](int c, int s) {
        uint32_t sA = sbase + (uint32_t)s * STAGE_B;
        uint32_t sB = sA + TILE_H * 2;
        #pragma unroll
        for (int i = 0; i < 2; i++) {
            cp16(sA + so[i], pA[i] + c * BK);
            cp16(sB + so[i], pB[i] + c * BK);
        }
        cp_commit();
    };

    // ldmatrix per-lane fragment offsets (bytes within a tile)
    uint32_t aoff = ((uint32_t)(32 * wm + (lane & 15)) * RSTRIDE + (lane >> 4) * 8) * 2;
    uint32_t boff = ((uint32_t)(64 * wn + (lane & 7) + 8 * (lane >> 4)) * RSTRIDE
                     + ((lane >> 3) & 1) * 8) * 2;

    float acc[2][8][4];
    #pragma unroll
    for (int i = 0; i < 2; i++)
        #pragma unroll
        for (int j = 0; j < 8; j++)
            #pragma unroll
            for (int q = 0; q < 4; q++) acc[i][j][q] = 0.f;

    load_chunk(0, 0);
    load_chunk(1, 1);

    for (int c = 0; c < NCHUNK; c++) {
        int s = c % 3;
        if (c < NCHUNK - 1)
            asm volatile("cp.async.wait_group 1;" ::: "memory");
        else
            asm volatile("cp.async.wait_group 0;" ::: "memory");
        __syncthreads();
        if (c + 2 < NCHUNK) load_chunk(c + 2, (c + 2) % 3);

        uint32_t As_b = sbase + (uint32_t)s * STAGE_B;
        uint32_t Bs_b = As_b + TILE_H * 2;
        #pragma unroll
        for (int kk = 0; kk < 2; kk++) {
            uint32_t kbb = (uint32_t)(kk * 16) * 2;
            uint32_t a[2][4], b[8][2];
            #pragma unroll
            for (int i = 0; i < 2; i++)
                LDSM4(a[i][0], a[i][1], a[i][2], a[i][3],
                      As_b + aoff + (uint32_t)i * (16 * RSTRIDE * 2) + kbb);
            #pragma unroll
            for (int jp = 0; jp < 4; jp++)
                LDSM4(b[2 * jp][0], b[2 * jp][1], b[2 * jp + 1][0], b[2 * jp + 1][1],
                      Bs_b + boff + (uint32_t)jp * (16 * RSTRIDE * 2) + kbb);
            #pragma unroll
            for (int i = 0; i < 2; i++)
                #pragma unroll
                for (int j = 0; j < 8; j++)
                    asm volatile(
                        "mma.sync.aligned.m16n8k16.row.col.f32.f16.f16.f32 "
                        "{%0,%1,%2,%3}, {%4,%5,%6,%7}, {%8,%9}, {%0,%1,%2,%3};"
                        : "+f"(acc[i][j][0]), "+f"(acc[i][j][1]),
                          "+f"(acc[i][j][2]), "+f"(acc[i][j][3])
                        : "r"(a[i][0]), "r"(a[i][1]), "r"(a[i][2]), "r"(a[i][3]),
                          "r"(b[j][0]), "r"(b[j][1]));
        }
    }

    int g = lane >> 2, tig = lane & 3;
    #pragma unroll
    for (int i = 0; i < 2; i++) {
        int rbase = r0 + 32 * wm + 16 * i + g;
        #pragma unroll
        for (int j = 0; j < 8; j++) {
            int col = o0 + 64 * wn + 8 * j + 2 * tig;
            float2 v0 = make_float2(acc[i][j][0], acc[i][j][1]);
            float2 v1 = make_float2(acc[i][j][2], acc[i][j][3]);
            *(float2*)(g_ys + (size_t)rbase * O_DIM + col) = v0;
            *(float2*)(g_ys + (size_t)(rbase + 8) * O_DIM + col) = v1;
        }
    }
}

// out[t,:] = w0*(ys[s0,:] + be[e0,:]) + w1*(ys[s1,:] + be[e1,:])
__global__ __launch_bounds__(256) void combine_kernel(const float* __restrict__ be,
                                                      float* __restrict__ out) {
    int t = blockIdx.x;
    int e0 = g_exp[2 * t], e1 = g_exp[2 * t + 1];
    float w0 = g_w[2 * t], w1 = g_w[2 * t + 1];
    size_t s0 = (size_t)e0 * CAP + g_rank[2 * t];
    size_t s1 = (size_t)e1 * CAP + g_rank[2 * t + 1];
    int o = threadIdx.x * 4;
    float4 y0 = *(const float4*)(g_ys + s0 * O_DIM + o);
    float4 y1 = *(const float4*)(g_ys + s1 * O_DIM + o);
    float4 b0 = *(const float4*)(be + (size_t)e0 * O_DIM + o);
    float4 b1 = *(const float4*)(be + (size_t)e1 * O_DIM + o);
    float4 r;
    r.x = w0 * (y0.x + b0.x) + w1 * (y1.x + b1.x);
    r.y = w0 * (y0.y + b0.y) + w1 * (y1.y + b1.y);
    r.z = w0 * (y0.z + b0.z) + w1 * (y1.z + b1.z);
    r.w = w0 * (y0.w + b0.w) + w1 * (y1.w + b1.w);
    *(float4*)(out + (size_t)t * O_DIM + o) = r;
}

extern "C" void kernel_launch(void* const* d_in, const int* in_sizes, int n_in,
                              void* d_out, int out_size) {
    const float* x  = (const float*)d_in[0];   // [4,2048,1024]
    const float* Wg = (const float*)d_in[1];   // [8,1024]
    const float* We = (const float*)d_in[2];   // [8,1024,1024]
    const float* be = (const float*)d_in[3];   // [8,1024]
    float* out = (float*)d_out;                // [4,2048,1024]

    static int smem_set = 0;
    if (!smem_set) {
        cudaFuncSetAttribute(expert_gemm_hmma,
                             cudaFuncAttributeMaxDynamicSharedMemorySize, GEMM_SMEM);
        smem_set = 1;
    }

    convert_we_kernel<<<4096, 256>>>(We);
    convert_x_kernel<<<T_TOKENS * D_DIM / 8 / 256, 256>>>(x);
    gate_kernel<<<T_TOKENS / 32, 256>>>(x, Wg);
    pad_idx_kernel<<<E_EXP, 128>>>();
    dim3 grid(O_DIM / 128, ROWS_CAP / 128, 1);
    expert_gemm_hmma<<<grid, 256, GEMM_SMEM>>>();
    combine_kernel<<<T_TOKENS, 256>>>(be, out);
}